// round 15
// baseline (speedup 1.0000x reference)
#include <cuda_runtime.h>

// ---------------------------------------------------------------------------
// Problem constants
// ---------------------------------------------------------------------------
constexpr int TFR   = 65536;
constexpr int KB9   = 9;
constexpr int BATCH = 32;
constexpr int LOUT  = (TFR - 1) * 4;            // 262140

constexpr int OT   = 980;                       // output samples per tile
constexpr int NT   = (LOUT + OT - 1) / OT;      // 268 tiles
constexpr int NTHR = 256;

// Interior geometry (compile-time): NFR=248, ngA=251, ngO=245, ROWS=255.
constexpr int I_OFF_S   = 0;                     // S plane: 255 x 4
constexpr int I_OFF_D   = 1020;                  // D plane: 255 x 4
constexpr int I_OFF_WAV = 2040;                  // wav plane: 251 x 4
constexpr int I_OFF_P0  = 3044;                  // P chunk planes: 248 x 4 each
constexpr int I_OFF_P1  = 4036;
constexpr int I_OFF_P2  = 5028;
constexpr int I_OFF_P3  = 6020;                  // P3 plane (EDGE only) / m4 overlay
constexpr int I_OFF_M4  = 6020;                  // m4[t] (DOUBLED) at P3 base + t
constexpr int I_SMW     = 7012;                  // 28048 bytes -> 8 CTAs/SM
constexpr int PPLANE    = 992;                   // words per P plane

// ---------------------------------------------------------------------------
// Compile-time twiddles (all angles multiples of pi/8)
// ---------------------------------------------------------------------------
#define HD __host__ __device__ __forceinline__

HD constexpr float cos8c(int m) {
    m &= 15;
    const int mm = m & 7;
    const float v =
        (mm == 0) ?  1.0f :
        (mm == 1) ?  0.92387953251128674f :
        (mm == 2) ?  0.70710678118654752f :
        (mm == 3) ?  0.38268343236508977f :
        (mm == 4) ?  0.0f :
        (mm == 5) ? -0.38268343236508977f :
        (mm == 6) ? -0.70710678118654752f :
                    -0.92387953251128674f;
    return (m & 8) ? -v : v;
}
HD constexpr float sin8c(int m) { return cos8c(m + 12); }
HD constexpr float wwinc(int n) { return 0.5f - 0.5f * cos8c(n); }   // hann(16)
HD constexpr float CSc(int k, int n) { return ((k == 0) ? 1.0f : 2.0f) * 0.0625f * cos8c(k * n) * wwinc(n); }
HD constexpr float envsum(int r) {
    return wwinc(r)      * wwinc(r)      + wwinc(r + 4)  * wwinc(r + 4)
         + wwinc(r + 8)  * wwinc(r + 8)  + wwinc(r + 12) * wwinc(r + 12);
}
HD constexpr float EINVc(int r) { return 1.0f / envsum(r); }
HD constexpr float CSF(int k, int n) { return CSc(k, n) * EINVc(n & 3); }
// m4 is stored DOUBLED; its accA coefficient carries the compensating 0.5.
HD constexpr float CSF4h(int n) { return CSF(4, n) * 0.5f; }
// P-row scale: window/16 (the extra 0.5 compensates the un-halved mv),
// optionally with 1/env folded (interior fast path).
HD constexpr float W8s(int n, bool fold) {
    return wwinc(n) * 0.0625f * (fold ? EINVc(n & 3) : 1.0f);
}

// Runtime tables (edge fallbacks only)
__constant__ float C8T[16] = { cos8c(0), cos8c(1), cos8c(2), cos8c(3), cos8c(4), cos8c(5), cos8c(6), cos8c(7),
                               cos8c(8), cos8c(9), cos8c(10), cos8c(11), cos8c(12), cos8c(13), cos8c(14), cos8c(15) };
__constant__ float W16T[16] = { wwinc(0), wwinc(1), wwinc(2), wwinc(3), wwinc(4), wwinc(5), wwinc(6), wwinc(7),
                                wwinc(8), wwinc(9), wwinc(10), wwinc(11), wwinc(12), wwinc(13), wwinc(14), wwinc(15) };

// ---------------------------------------------------------------------------
// Phase-A accumulator (env folded; m4 operand arrives doubled).
// ---------------------------------------------------------------------------
template<int JJ>
__device__ __forceinline__ void accA(const float4 u0, const float4 u1, const float m4,
                                     float& y0, float& y1, float& y2, float& y3)
{
    { constexpr int n = 4 * JJ + 0;
      if (CSF(0,n)  != 0.f) y0 = fmaf(u0.x, CSF(0,n),  y0);
      if (CSF(1,n)  != 0.f) y0 = fmaf(u0.y, CSF(1,n),  y0);
      if (CSF(2,n)  != 0.f) y0 = fmaf(u0.z, CSF(2,n),  y0);
      if (CSF(3,n)  != 0.f) y0 = fmaf(u0.w, CSF(3,n),  y0);
      if (CSF4h(n)  != 0.f) y0 = fmaf(m4,   CSF4h(n),  y0); }
    { constexpr int n = 4 * JJ + 1;
      if (CSF(0,n)  != 0.f) y1 = fmaf(u1.x, CSF(0,n),  y1);
      if (CSF(1,n)  != 0.f) y1 = fmaf(u1.y, CSF(1,n),  y1);
      if (CSF(2,n)  != 0.f) y1 = fmaf(u1.z, CSF(2,n),  y1);
      if (CSF(3,n)  != 0.f) y1 = fmaf(u1.w, CSF(3,n),  y1); }
    { constexpr int n = 4 * JJ + 2;
      if (CSF(0,n)  != 0.f) y2 = fmaf(u0.x, CSF(0,n),  y2);
      if (CSF(1,n)  != 0.f) y2 = fmaf(u0.y, CSF(1,n),  y2);
      if (CSF(2,n)  != 0.f) y2 = fmaf(u0.z, CSF(2,n),  y2);
      if (CSF(3,n)  != 0.f) y2 = fmaf(u0.w, CSF(3,n),  y2);
      if (CSF4h(n)  != 0.f) y2 = fmaf(m4,   CSF4h(n),  y2); }
    { constexpr int n = 4 * JJ + 3;
      if (CSF(0,n)  != 0.f) y3 = fmaf(u1.x, CSF(0,n),  y3);
      if (CSF(1,n)  != 0.f) y3 = fmaf(u1.y, CSF(1,n),  y3);
      if (CSF(2,n)  != 0.f) y3 = fmaf(u1.z, CSF(2,n),  y3);
      if (CSF(3,n)  != 0.f) y3 = fmaf(u1.w, CSF(3,n),  y3); }
}

// ---------------------------------------------------------------------------
// B1 frame processing, FFT-folded; result in registers.
// mv is UNSCALED (S+-D, m4 doubled); the compensating 0.5 lives in W8s.
// FOLD=true folds 1/env into the P-row scales (interior fast path only).
// ---------------------------------------------------------------------------
template<bool FOLD>
__device__ __forceinline__ void processFrame(const float4 A0, const float4 A1,
                                             const float4 A2, const float4 A3,
                                             const float4 MS, const float4 MD, const float m4v,
                                             float4& R0, float4& R1, float4& R2, float4& R3)
{
    constexpr float c1 = 0.92387953251128674f;   // cos(pi/8)
    constexpr float c2 = 0.70710678118654752f;   // cos(pi/4)
    constexpr float c3 = 0.38268343236508977f;   // cos(3pi/8)

    const float x8 = A2.x;
    const float e1 = wwinc(1) * (A0.y + A3.w), o1 = wwinc(1) * (A0.y - A3.w);
    const float e2 = wwinc(2) * (A0.z + A3.z), o2 = wwinc(2) * (A0.z - A3.z);
    const float e3 = wwinc(3) * (A0.w + A3.y), o3 = wwinc(3) * (A0.w - A3.y);
    const float e4 = wwinc(4) * (A1.x + A3.x), o4 = wwinc(4) * (A1.x - A3.x);
    const float e5 = wwinc(5) * (A1.y + A2.w), o5 = wwinc(5) * (A1.y - A2.w);
    const float e6 = wwinc(6) * (A1.z + A2.z), o6 = wwinc(6) * (A1.z - A2.z);
    const float e7 = wwinc(7) * (A1.w + A2.y), o7 = wwinc(7) * (A1.w - A2.y);

    const float es1 = e1 + e7, es2 = e2 + e6, es3 = e3 + e5;
    const float ed1 = e1 - e7, ed2 = e2 - e6, ed3 = e3 - e5;
    const float os1 = o1 + o7, os2 = o2 + o6, os3 = o3 + o5;
    const float od1 = o1 - o7, od2 = o2 - o6, od3 = o3 - o5;

    float re[9], im[9];
    {   const float t1 = c2 * (es1 - es3);
        const float t2 = x8 - e4, t3 = x8 + e4;
        const float q  = es1 + es3;
        const float Aa = t3 + es2;
        re[0] = Aa + q;  re[8] = Aa - q;
        re[2] = t2 + t1; re[6] = t2 - t1;
        re[4] = t3 - es2; }
    {   const float m  = ed2 * c2;
        const float v  = m - x8, w = -m - x8;
        const float u  = fmaf(ed1, c1,  ed3 * c3);
        const float u2 = fmaf(ed1, c3, -(ed3 * c1));
        re[1] = v + u;  re[7] = v - u;
        re[3] = w + u2; re[5] = w - u2; }
    {   const float a  = fmaf(os1, c3,  os3 * c1);
        const float b  = fmaf(os2, c2,  o4);
        const float a2 = fmaf(os1, c1, -(os3 * c3));
        const float b2 = fmaf(os2, c2, -o4);
        im[1] = -(a + b);   im[3] = -(a2 + b2);
        im[5] = b2 - a2;    im[7] = b - a; }
    {   const float t4 = c2 * (od1 + od3);
        im[2] = -(t4 + od2); im[6] = od2 - t4; im[4] = od3 - od1; }

    // UNSCALED magnitudes (2x true values); 0.5 compensated in W8s.
    float mv[9];
    mv[0] = MS.x + MD.x;  mv[8] = MS.x - MD.x;
    mv[1] = MS.y + MD.y;  mv[7] = MS.y - MD.y;
    mv[2] = MS.z + MD.z;  mv[6] = MS.z - MD.z;
    mv[3] = MS.w + MD.w;  mv[5] = MS.w - MD.w;
    mv[4] = m4v;          // arrives doubled

    float ca[9], sa[9];
    ca[0] = copysignf(mv[0], re[0]);
    ca[8] = copysignf(mv[8], re[8]);
    #pragma unroll
    for (int k = 1; k < 8; k++) {
        const float n2 = fmaf(re[k], re[k], im[k] * im[k]);
        if (n2 > 0.f) {
            const float u = mv[k] * rsqrtf(n2);
            ca[k] = re[k] * u;
            sa[k] = im[k] * u;
        } else {
            ca[k] = mv[k];
            sa[k] = 0.f;
        }
    }

    const float Ai1 = ca[1] + ca[7], Ai2 = ca[2] + ca[6], Ai3 = ca[3] + ca[5];
    const float Ci1 = ca[1] - ca[7], Ci2 = ca[2] - ca[6], Ci3 = ca[3] - ca[5];
    const float Si1 = sa[1] + sa[7], Si2 = sa[2] + sa[6], Si3 = sa[3] + sa[5];
    const float Di1 = sa[1] - sa[7], Di2 = sa[2] - sa[6], Di3 = sa[3] - sa[5];
    const float z2  = 0.5f * (ca[0] + ca[8]);
    const float z2p = 0.5f * (ca[0] - ca[8]);
    const float ca4 = ca[4], sa4 = sa[4];

    const float h1 = c2 * (Ai1 - Ai3);
    const float h2 = c2 * (Di1 + Di3);
    const float za = z2 - ca4, zb = z2 + ca4;
    const float E2 = za + h1, E6 = za - h1, E4 = zb - Ai2;
    const float O2 = h2 + Di2, O6 = h2 - Di2, O4 = Di1 - Di3;
    const float s8  = (zb + Ai2) - (Ai1 + Ai3);
    const float s2  = E2 - O2, s14 = E2 + O2;
    const float s4  = E4 - O4, s12 = E4 + O4;
    const float s6  = E6 - O6, s10 = E6 + O6;

    const float mC  = Ci2 * c2;
    const float uE  = fmaf(Ci1, c1,  Ci3 * c3);
    const float u2E = fmaf(Ci1, c3, -(Ci3 * c1));
    const float ta  = z2p + mC, tb = z2p - mC;
    const float E1 = ta + uE, E7 = ta - uE, E3 = tb + u2E, E5 = tb - u2E;
    const float nS  = Si2 * c2;
    const float vO  = fmaf(Si1, c3,  Si3 * c1);
    const float v2O = fmaf(Si1, c1, -(Si3 * c3));
    const float wo = nS + sa4, w2o = nS - sa4;
    const float O1 = vO + wo, O7 = vO - wo, O3 = v2O + w2o, O5 = v2O - w2o;
    const float s1  = E1 - O1, s15 = E1 + O1;
    const float s3  = E3 - O3, s13 = E3 + O3;
    const float s5  = E5 - O5, s11 = E5 + O5;
    const float s7  = E7 - O7, s9  = E7 + O7;

    R0 = make_float4(0.f,               W8s(1,FOLD)*s1,   W8s(2,FOLD)*s2,   W8s(3,FOLD)*s3);
    R1 = make_float4(W8s(4,FOLD)*s4,    W8s(5,FOLD)*s5,   W8s(6,FOLD)*s6,   W8s(7,FOLD)*s7);
    R2 = make_float4(W8s(8,FOLD)*s8,    W8s(9,FOLD)*s9,   W8s(10,FOLD)*s10, W8s(11,FOLD)*s11);
    R3 = make_float4(W8s(12,FOLD)*s12,  W8s(13,FOLD)*s13, W8s(14,FOLD)*s14, W8s(15,FOLD)*s15);
}

// ---------------------------------------------------------------------------
// Fused kernel, 8 CTAs/SM. Interior CTAs: constant geometry; B1/B2 are
// remapped (thread t <-> frame/group t-3) so the B1 mag row and B2's q3 are
// register-resident. Edge CTAs: bounds-checked body on the same planes.
// ---------------------------------------------------------------------------
__global__ void __launch_bounds__(NTHR, 8)
glim_kernel(const float* __restrict__ mag, float* __restrict__ out)
{
    __shared__ __align__(16) float sm[I_SMW];

    const int tid = threadIdx.x;
    const int bx  = blockIdx.x;
    const int b   = blockIdx.y;
    const float* magb = mag + (size_t)b * (KB9 * TFR);

    if (bx > 0 && bx < NT - 1) {
        // ================= INTERIOR body =================
        const int s0  = bx * OT;
        const int F0  = s0 >> 2;
        const int tM0 = F0 - 4;
        // constants: NFR=248, ngA=251, ngO=245, ROWS=255

        // ---- stage (single pass); keep own row in regs; m4 doubled ----
        float4 rS, rD; float rM4;
        if (tid < 255) {
            const float* gp = magb + (tM0 + tid);
            const float a0 = __ldg(gp);            const float a8 = __ldg(gp + 8 * TFR);
            const float a1 = __ldg(gp + 1 * TFR);  const float a7 = __ldg(gp + 7 * TFR);
            const float a2 = __ldg(gp + 2 * TFR);  const float a6 = __ldg(gp + 6 * TFR);
            const float a3 = __ldg(gp + 3 * TFR);  const float a5 = __ldg(gp + 5 * TFR);
            rS  = make_float4(a0 + a8, a1 + a7, a2 + a6, a3 + a5);
            rD  = make_float4(a0 - a8, a1 - a7, a2 - a6, a3 - a5);
            rM4 = 2.f * __ldg(gp + 4 * TFR);
            *reinterpret_cast<float4*>(sm + I_OFF_S + tid * 4) = rS;
            *reinterpret_cast<float4*>(sm + I_OFF_D + tid * 4) = rD;
            sm[I_OFF_M4 + tid] = rM4;
        }
        __syncthreads();

        // ---- Phase A: own row from regs, rows g+1..g+3 from smem ----
        float ay0 = 0.f, ay1 = 0.f, ay2 = 0.f, ay3 = 0.f;
        if (tid < 251) {
            const int g = tid;
            accA<3>(rS, rD, rM4, ay0, ay1, ay2, ay3);
            {   const float4 u0 = *reinterpret_cast<const float4*>(sm + I_OFF_S + (g + 1) * 4);
                const float4 u1 = *reinterpret_cast<const float4*>(sm + I_OFF_D + (g + 1) * 4);
                accA<2>(u0, u1, sm[I_OFF_M4 + g + 1], ay0, ay1, ay2, ay3); }
            {   const float4 u0 = *reinterpret_cast<const float4*>(sm + I_OFF_S + (g + 2) * 4);
                const float4 u1 = *reinterpret_cast<const float4*>(sm + I_OFF_D + (g + 2) * 4);
                accA<1>(u0, u1, sm[I_OFF_M4 + g + 2], ay0, ay1, ay2, ay3); }
            {   const float4 u0 = *reinterpret_cast<const float4*>(sm + I_OFF_S + (g + 3) * 4);
                const float4 u1 = *reinterpret_cast<const float4*>(sm + I_OFF_D + (g + 3) * 4);
                accA<0>(u0, u1, sm[I_OFF_M4 + g + 3], ay0, ay1, ay2, ay3); }
            *reinterpret_cast<float4*>(sm + I_OFF_WAV + g * 4) = make_float4(ay0, ay1, ay2, ay3);
        }
        __syncthreads();

        // ---- Phase B1 (remapped): thread t handles frame f = t-3 ----
        // A3 = own wav group (ay); MS/MD/m4 = own staged row t (= mag of
        // frame f+3). Only wav rows f..f+2 come from smem.
        float4 R3own;
        if (tid >= 3 && tid < 251) {
            const int f = tid - 3;
            const float4 A0 = *reinterpret_cast<const float4*>(sm + I_OFF_WAV + f * 4);
            const float4 A1 = *reinterpret_cast<const float4*>(sm + I_OFF_WAV + (f + 1) * 4);
            const float4 A2 = *reinterpret_cast<const float4*>(sm + I_OFF_WAV + (f + 2) * 4);
            const float4 A3 = make_float4(ay0, ay1, ay2, ay3);
            float4 R0, R1, R2, R3;
            processFrame<true>(A0, A1, A2, A3, rS, rD, rM4, R0, R1, R2, R3);
            *reinterpret_cast<float4*>(sm + I_OFF_P0 + f * 4) = R0;
            *reinterpret_cast<float4*>(sm + I_OFF_P1 + f * 4) = R1;
            *reinterpret_cast<float4*>(sm + I_OFF_P2 + f * 4) = R2;
            R3own = R3;                                      // P3 plane never stored
        }
        __syncthreads();

        // ---- Phase B2 (remapped): thread t outputs group g = t-3 ----
        if (tid >= 3 && tid < 248) {
            const int g = tid - 3;
            const float4 q2 = *reinterpret_cast<const float4*>(sm + I_OFF_P2 + (g + 1) * 4);
            const float4 q1 = *reinterpret_cast<const float4*>(sm + I_OFF_P1 + (g + 2) * 4);
            const float4 q0 = *reinterpret_cast<const float4*>(sm + I_OFF_P0 + (g + 3) * 4);
            float* outb = out + (size_t)b * LOUT + s0;
            *reinterpret_cast<float4*>(outb + 4 * g) = make_float4(
                (q0.x + q1.x) + (q2.x + R3own.x),
                (q0.y + q1.y) + (q2.y + R3own.y),
                (q0.z + q1.z) + (q2.z + R3own.z),
                (q0.w + q1.w) + (q2.w + R3own.w));
        }
    } else {
        // ================= EDGE body (tiles 0 and NT-1) =================
        const int s0   = bx * OT;
        const int nout = min(OT, LOUT - s0);
        const int F0   = s0 >> 2;
        const int TLO  = max(0, F0 - 1);
        const int THI  = min(TFR - 1, (s0 + nout + 7) >> 2);
        const int NFR  = THI - TLO + 1;
        const int tM0  = TLO - 3;
        const int ROWS = NFR + 7;                 // <= 254

        if (tid < ROWS) {
            const int tg = tM0 + tid;
            float4 S, D; float m4;
            if (tg >= 0 && tg < TFR) {
                const float* gp = magb + tg;
                const float a0 = __ldg(gp);            const float a8 = __ldg(gp + 8 * TFR);
                const float a1 = __ldg(gp + 1 * TFR);  const float a7 = __ldg(gp + 7 * TFR);
                const float a2 = __ldg(gp + 2 * TFR);  const float a6 = __ldg(gp + 6 * TFR);
                const float a3 = __ldg(gp + 3 * TFR);  const float a5 = __ldg(gp + 5 * TFR);
                m4 = 2.f * __ldg(gp + 4 * TFR);
                S = make_float4(a0 + a8, a1 + a7, a2 + a6, a3 + a5);
                D = make_float4(a0 - a8, a1 - a7, a2 - a6, a3 - a5);
            } else {
                S = make_float4(0.f, 0.f, 0.f, 0.f);
                D = S; m4 = 0.f;
            }
            *reinterpret_cast<float4*>(sm + I_OFF_S + tid * 4) = S;
            *reinterpret_cast<float4*>(sm + I_OFF_D + tid * 4) = D;
            sm[I_OFF_M4 + tid] = m4;              // doubled
        }
        __syncthreads();

        // Phase A (m4 plane intact here; holds 2*m4)
        const int ngA = NFR + 3;
        if (tid < ngA) {
            const int g     = tid;
            const int jbase = 4 * TLO - 8 + 4 * g;
            const int X     = TLO + g;
            if (jbase >= 0 && jbase + 3 < LOUT && X >= 3 && X <= TFR - 1) {
                float y0 = 0.f, y1 = 0.f, y2 = 0.f, y3 = 0.f;
                {   const float4 u0 = *reinterpret_cast<const float4*>(sm + I_OFF_S + g * 4);
                    const float4 u1 = *reinterpret_cast<const float4*>(sm + I_OFF_D + g * 4);
                    accA<3>(u0, u1, sm[I_OFF_M4 + g], y0, y1, y2, y3); }
                {   const float4 u0 = *reinterpret_cast<const float4*>(sm + I_OFF_S + (g + 1) * 4);
                    const float4 u1 = *reinterpret_cast<const float4*>(sm + I_OFF_D + (g + 1) * 4);
                    accA<2>(u0, u1, sm[I_OFF_M4 + g + 1], y0, y1, y2, y3); }
                {   const float4 u0 = *reinterpret_cast<const float4*>(sm + I_OFF_S + (g + 2) * 4);
                    const float4 u1 = *reinterpret_cast<const float4*>(sm + I_OFF_D + (g + 2) * 4);
                    accA<1>(u0, u1, sm[I_OFF_M4 + g + 2], y0, y1, y2, y3); }
                {   const float4 u0 = *reinterpret_cast<const float4*>(sm + I_OFF_S + (g + 3) * 4);
                    const float4 u1 = *reinterpret_cast<const float4*>(sm + I_OFF_D + (g + 3) * 4);
                    accA<0>(u0, u1, sm[I_OFF_M4 + g + 3], y0, y1, y2, y3); }
                *reinterpret_cast<float4*>(sm + I_OFF_WAV + g * 4) = make_float4(y0, y1, y2, y3);
            } else {
                float* wp = sm + I_OFF_WAV + g * 4;
                for (int r = 0; r < 4; r++) {
                    const int jg = jbase + r;
                    const int jr = (jg < 0) ? -jg : ((jg >= LOUT) ? 2 * LOUT - 2 - jg : jg);
                    const int p  = jr + 8;
                    const int Xp = p >> 2;
                    const int rr = p & 3;
                    float acc = 0.f, env = 0.f;
                    for (int jj = 0; jj < 4; jj++) {
                        const int tt = Xp - jj;
                        if (tt < 0 || tt >= TFR) continue;
                        const int n = rr + 4 * jj;
                        const float w = W16T[n];
                        const int row = tt - tM0;
                        const float* sp = sm + I_OFF_S + row * 4;
                        const float* dp = sm + I_OFF_D + row * 4;
                        float ssum;
                        if (n & 1) {
                            ssum = dp[0]
                                 + 2.f * (dp[1] * C8T[n & 15] + dp[2] * C8T[(2 * n) & 15] + dp[3] * C8T[(3 * n) & 15]);
                        } else {
                            // m4 plane holds 2*m4, which IS the needed
                            // coefficient (2 * m4 * cos): no extra factor.
                            ssum = sp[0]
                                 + 2.f * (sp[1] * C8T[n & 15] + sp[2] * C8T[(2 * n) & 15] + sp[3] * C8T[(3 * n) & 15])
                                 + sm[I_OFF_M4 + row] * C8T[(4 * n) & 15];
                        }
                        acc = fmaf(ssum, 0.0625f * w, acc);
                        env = fmaf(w, w, env);
                    }
                    wp[r] = acc / env;
                }
            }
        }
        __syncthreads();

        // Phase B1: m4 from GLOBAL (doubled); its smem slot becomes P3.
        if (tid < NFR) {
            const int f = tid;
            const float4 A0 = *reinterpret_cast<const float4*>(sm + I_OFF_WAV + f * 4);
            const float4 A1 = *reinterpret_cast<const float4*>(sm + I_OFF_WAV + (f + 1) * 4);
            const float4 A2 = *reinterpret_cast<const float4*>(sm + I_OFF_WAV + (f + 2) * 4);
            const float4 A3 = *reinterpret_cast<const float4*>(sm + I_OFF_WAV + (f + 3) * 4);
            const float4 MS = *reinterpret_cast<const float4*>(sm + I_OFF_S + (f + 3) * 4);
            const float4 MD = *reinterpret_cast<const float4*>(sm + I_OFF_D + (f + 3) * 4);
            const float m4v = 2.f * __ldg(magb + 4 * TFR + (tM0 + f + 3));
            float4 R0, R1, R2, R3;
            processFrame<false>(A0, A1, A2, A3, MS, MD, m4v, R0, R1, R2, R3);
            *reinterpret_cast<float4*>(sm + I_OFF_P0 + f * 4) = R0;
            *reinterpret_cast<float4*>(sm + I_OFF_P1 + f * 4) = R1;
            *reinterpret_cast<float4*>(sm + I_OFF_P2 + f * 4) = R2;
            *reinterpret_cast<float4*>(sm + I_OFF_P3 + f * 4) = R3;
        }
        __syncthreads();

        // Phase B2
        const int ngO = (nout + 3) >> 2;
        float* outb = out + (size_t)b * LOUT + s0;
        if (tid < ngO) {
            const int g = tid;
            const int X = F0 + g + 2;
            const bool wholeGroup = (4 * g + 3 < nout);
            if (wholeGroup && X - 3 >= TLO && X <= THI) {
                const int Rb = X - TLO - 3;
                const float4 q3 = *reinterpret_cast<const float4*>(sm + I_OFF_P3 + Rb * 4);
                const float4 q2 = *reinterpret_cast<const float4*>(sm + I_OFF_P2 + (Rb + 1) * 4);
                const float4 q1 = *reinterpret_cast<const float4*>(sm + I_OFF_P1 + (Rb + 2) * 4);
                const float4 q0 = *reinterpret_cast<const float4*>(sm + I_OFF_P0 + (Rb + 3) * 4);
                *reinterpret_cast<float4*>(outb + 4 * g) = make_float4(
                    ((q0.x + q1.x) + (q2.x + q3.x)) * EINVc(0),
                    ((q0.y + q1.y) + (q2.y + q3.y)) * EINVc(1),
                    ((q0.z + q1.z) + (q2.z + q3.z)) * EINVc(2),
                    ((q0.w + q1.w) + (q2.w + q3.w)) * EINVc(3));
            } else {
                for (int r = 0; r < 4; r++) {
                    const int so = 4 * g + r;
                    if (so >= nout) break;
                    const int s  = s0 + so;
                    const int p  = s + 8;
                    const int Xp = p >> 2;
                    const int rr = p & 3;
                    float acc = 0.f, env = 0.f;
                    for (int jj = 0; jj < 4; jj++) {
                        const int tt = Xp - jj;
                        if (tt < TLO || tt > THI) continue;
                        const int n = rr + 4 * jj;
                        const float w = W16T[n];
                        acc += sm[I_OFF_P0 + (n >> 2) * PPLANE + (tt - TLO) * 4 + (n & 3)];
                        env = fmaf(w, w, env);
                    }
                    outb[so] = acc / env;
                }
            }
        }
    }
}

// ---------------------------------------------------------------------------
extern "C" void kernel_launch(void* const* d_in, const int* in_sizes, int n_in,
                              void* d_out, int out_size)
{
    (void)in_sizes; (void)n_in; (void)out_size;
    const float* mag = (const float*)d_in[0];
    float* out = (float*)d_out;
    // Maximize shared carveout; 28.0 KB/CTA -> 8 CTAs/SM.
    cudaFuncSetAttribute(glim_kernel, cudaFuncAttributePreferredSharedMemoryCarveout, 100);
    dim3 grid(NT, BATCH);
    glim_kernel<<<grid, NTHR>>>(mag, out);
}

// round 16
// speedup vs baseline: 1.0360x; 1.0360x over previous
#include <cuda_runtime.h>

// ---------------------------------------------------------------------------
// Problem constants
// ---------------------------------------------------------------------------
constexpr int TFR   = 65536;
constexpr int KB9   = 9;
constexpr int BATCH = 32;
constexpr int LOUT  = (TFR - 1) * 4;            // 262140

// OT chosen so grid = NT*BATCH = 296*32 = 9472 = 148 SMs * 8 CTAs * 8 waves
// exactly (no partial final wave at 8 CTAs/SM occupancy).
constexpr int OT   = 888;                       // output samples per tile
constexpr int NT   = (LOUT + OT - 1) / OT;      // 296 tiles
constexpr int NTHR = 256;

// Interior geometry (compile-time): NFR=225, ngA=228, ngO=222, ROWS=232.
constexpr int I_OFF_S   = 0;                     // S plane: 232 x 4
constexpr int I_OFF_D   = 928;                   // D plane: 232 x 4
constexpr int I_OFF_WAV = 1856;                  // wav plane: 228 x 4
constexpr int I_OFF_P0  = 2768;                  // P chunk planes: 225 x 4 each
constexpr int I_OFF_P1  = 3668;
constexpr int I_OFF_P2  = 4568;
constexpr int I_OFF_P3  = 5468;                  // P3 plane (EDGE only) / m4 overlay
constexpr int I_OFF_M4  = 5468;                  // m4[t] (DOUBLED) at P3 base + t
constexpr int I_SMW     = 6368;                  // 25472 bytes -> 8 CTAs/SM
constexpr int PPLANE    = 900;                   // words per P plane

// ---------------------------------------------------------------------------
// Compile-time twiddles (all angles multiples of pi/8)
// ---------------------------------------------------------------------------
#define HD __host__ __device__ __forceinline__

HD constexpr float cos8c(int m) {
    m &= 15;
    const int mm = m & 7;
    const float v =
        (mm == 0) ?  1.0f :
        (mm == 1) ?  0.92387953251128674f :
        (mm == 2) ?  0.70710678118654752f :
        (mm == 3) ?  0.38268343236508977f :
        (mm == 4) ?  0.0f :
        (mm == 5) ? -0.38268343236508977f :
        (mm == 6) ? -0.70710678118654752f :
                    -0.92387953251128674f;
    return (m & 8) ? -v : v;
}
HD constexpr float sin8c(int m) { return cos8c(m + 12); }
HD constexpr float wwinc(int n) { return 0.5f - 0.5f * cos8c(n); }   // hann(16)
HD constexpr float CSc(int k, int n) { return ((k == 0) ? 1.0f : 2.0f) * 0.0625f * cos8c(k * n) * wwinc(n); }
HD constexpr float envsum(int r) {
    return wwinc(r)      * wwinc(r)      + wwinc(r + 4)  * wwinc(r + 4)
         + wwinc(r + 8)  * wwinc(r + 8)  + wwinc(r + 12) * wwinc(r + 12);
}
HD constexpr float EINVc(int r) { return 1.0f / envsum(r); }
HD constexpr float CSF(int k, int n) { return CSc(k, n) * EINVc(n & 3); }
// m4 is stored DOUBLED; its accA coefficient carries the compensating 0.5.
HD constexpr float CSF4h(int n) { return CSF(4, n) * 0.5f; }
// P-row scale: window/16 (the extra 0.5 compensates the un-halved mv),
// optionally with 1/env folded (interior fast path).
HD constexpr float W8s(int n, bool fold) {
    return wwinc(n) * 0.0625f * (fold ? EINVc(n & 3) : 1.0f);
}

// Runtime tables (edge fallbacks only)
__constant__ float C8T[16] = { cos8c(0), cos8c(1), cos8c(2), cos8c(3), cos8c(4), cos8c(5), cos8c(6), cos8c(7),
                               cos8c(8), cos8c(9), cos8c(10), cos8c(11), cos8c(12), cos8c(13), cos8c(14), cos8c(15) };
__constant__ float W16T[16] = { wwinc(0), wwinc(1), wwinc(2), wwinc(3), wwinc(4), wwinc(5), wwinc(6), wwinc(7),
                                wwinc(8), wwinc(9), wwinc(10), wwinc(11), wwinc(12), wwinc(13), wwinc(14), wwinc(15) };

// ---------------------------------------------------------------------------
// Phase-A accumulator (env folded; m4 operand arrives doubled).
// ---------------------------------------------------------------------------
template<int JJ>
__device__ __forceinline__ void accA(const float4 u0, const float4 u1, const float m4,
                                     float& y0, float& y1, float& y2, float& y3)
{
    { constexpr int n = 4 * JJ + 0;
      if (CSF(0,n)  != 0.f) y0 = fmaf(u0.x, CSF(0,n),  y0);
      if (CSF(1,n)  != 0.f) y0 = fmaf(u0.y, CSF(1,n),  y0);
      if (CSF(2,n)  != 0.f) y0 = fmaf(u0.z, CSF(2,n),  y0);
      if (CSF(3,n)  != 0.f) y0 = fmaf(u0.w, CSF(3,n),  y0);
      if (CSF4h(n)  != 0.f) y0 = fmaf(m4,   CSF4h(n),  y0); }
    { constexpr int n = 4 * JJ + 1;
      if (CSF(0,n)  != 0.f) y1 = fmaf(u1.x, CSF(0,n),  y1);
      if (CSF(1,n)  != 0.f) y1 = fmaf(u1.y, CSF(1,n),  y1);
      if (CSF(2,n)  != 0.f) y1 = fmaf(u1.z, CSF(2,n),  y1);
      if (CSF(3,n)  != 0.f) y1 = fmaf(u1.w, CSF(3,n),  y1); }
    { constexpr int n = 4 * JJ + 2;
      if (CSF(0,n)  != 0.f) y2 = fmaf(u0.x, CSF(0,n),  y2);
      if (CSF(1,n)  != 0.f) y2 = fmaf(u0.y, CSF(1,n),  y2);
      if (CSF(2,n)  != 0.f) y2 = fmaf(u0.z, CSF(2,n),  y2);
      if (CSF(3,n)  != 0.f) y2 = fmaf(u0.w, CSF(3,n),  y2);
      if (CSF4h(n)  != 0.f) y2 = fmaf(m4,   CSF4h(n),  y2); }
    { constexpr int n = 4 * JJ + 3;
      if (CSF(0,n)  != 0.f) y3 = fmaf(u1.x, CSF(0,n),  y3);
      if (CSF(1,n)  != 0.f) y3 = fmaf(u1.y, CSF(1,n),  y3);
      if (CSF(2,n)  != 0.f) y3 = fmaf(u1.z, CSF(2,n),  y3);
      if (CSF(3,n)  != 0.f) y3 = fmaf(u1.w, CSF(3,n),  y3); }
}

// ---------------------------------------------------------------------------
// B1 frame processing, FFT-folded; result in registers.
// mv is UNSCALED (S+-D, m4 doubled); the compensating 0.5 lives in W8s.
// FOLD=true folds 1/env into the P-row scales (interior fast path only).
// ---------------------------------------------------------------------------
template<bool FOLD>
__device__ __forceinline__ void processFrame(const float4 A0, const float4 A1,
                                             const float4 A2, const float4 A3,
                                             const float4 MS, const float4 MD, const float m4v,
                                             float4& R0, float4& R1, float4& R2, float4& R3)
{
    constexpr float c1 = 0.92387953251128674f;   // cos(pi/8)
    constexpr float c2 = 0.70710678118654752f;   // cos(pi/4)
    constexpr float c3 = 0.38268343236508977f;   // cos(3pi/8)

    const float x8 = A2.x;
    const float e1 = wwinc(1) * (A0.y + A3.w), o1 = wwinc(1) * (A0.y - A3.w);
    const float e2 = wwinc(2) * (A0.z + A3.z), o2 = wwinc(2) * (A0.z - A3.z);
    const float e3 = wwinc(3) * (A0.w + A3.y), o3 = wwinc(3) * (A0.w - A3.y);
    const float e4 = wwinc(4) * (A1.x + A3.x), o4 = wwinc(4) * (A1.x - A3.x);
    const float e5 = wwinc(5) * (A1.y + A2.w), o5 = wwinc(5) * (A1.y - A2.w);
    const float e6 = wwinc(6) * (A1.z + A2.z), o6 = wwinc(6) * (A1.z - A2.z);
    const float e7 = wwinc(7) * (A1.w + A2.y), o7 = wwinc(7) * (A1.w - A2.y);

    const float es1 = e1 + e7, es2 = e2 + e6, es3 = e3 + e5;
    const float ed1 = e1 - e7, ed2 = e2 - e6, ed3 = e3 - e5;
    const float os1 = o1 + o7, os2 = o2 + o6, os3 = o3 + o5;
    const float od1 = o1 - o7, od2 = o2 - o6, od3 = o3 - o5;

    float re[9], im[9];
    {   const float t1 = c2 * (es1 - es3);
        const float t2 = x8 - e4, t3 = x8 + e4;
        const float q  = es1 + es3;
        const float Aa = t3 + es2;
        re[0] = Aa + q;  re[8] = Aa - q;
        re[2] = t2 + t1; re[6] = t2 - t1;
        re[4] = t3 - es2; }
    {   const float m  = ed2 * c2;
        const float v  = m - x8, w = -m - x8;
        const float u  = fmaf(ed1, c1,  ed3 * c3);
        const float u2 = fmaf(ed1, c3, -(ed3 * c1));
        re[1] = v + u;  re[7] = v - u;
        re[3] = w + u2; re[5] = w - u2; }
    {   const float a  = fmaf(os1, c3,  os3 * c1);
        const float b  = fmaf(os2, c2,  o4);
        const float a2 = fmaf(os1, c1, -(os3 * c3));
        const float b2 = fmaf(os2, c2, -o4);
        im[1] = -(a + b);   im[3] = -(a2 + b2);
        im[5] = b2 - a2;    im[7] = b - a; }
    {   const float t4 = c2 * (od1 + od3);
        im[2] = -(t4 + od2); im[6] = od2 - t4; im[4] = od3 - od1; }

    // UNSCALED magnitudes (2x true values); 0.5 compensated in W8s.
    float mv[9];
    mv[0] = MS.x + MD.x;  mv[8] = MS.x - MD.x;
    mv[1] = MS.y + MD.y;  mv[7] = MS.y - MD.y;
    mv[2] = MS.z + MD.z;  mv[6] = MS.z - MD.z;
    mv[3] = MS.w + MD.w;  mv[5] = MS.w - MD.w;
    mv[4] = m4v;          // arrives doubled

    float ca[9], sa[9];
    ca[0] = copysignf(mv[0], re[0]);
    ca[8] = copysignf(mv[8], re[8]);
    #pragma unroll
    for (int k = 1; k < 8; k++) {
        const float n2 = fmaf(re[k], re[k], im[k] * im[k]);
        if (n2 > 0.f) {
            const float u = mv[k] * rsqrtf(n2);
            ca[k] = re[k] * u;
            sa[k] = im[k] * u;
        } else {
            ca[k] = mv[k];
            sa[k] = 0.f;
        }
    }

    const float Ai1 = ca[1] + ca[7], Ai2 = ca[2] + ca[6], Ai3 = ca[3] + ca[5];
    const float Ci1 = ca[1] - ca[7], Ci2 = ca[2] - ca[6], Ci3 = ca[3] - ca[5];
    const float Si1 = sa[1] + sa[7], Si2 = sa[2] + sa[6], Si3 = sa[3] + sa[5];
    const float Di1 = sa[1] - sa[7], Di2 = sa[2] - sa[6], Di3 = sa[3] - sa[5];
    const float z2  = 0.5f * (ca[0] + ca[8]);
    const float z2p = 0.5f * (ca[0] - ca[8]);
    const float ca4 = ca[4], sa4 = sa[4];

    const float h1 = c2 * (Ai1 - Ai3);
    const float h2 = c2 * (Di1 + Di3);
    const float za = z2 - ca4, zb = z2 + ca4;
    const float E2 = za + h1, E6 = za - h1, E4 = zb - Ai2;
    const float O2 = h2 + Di2, O6 = h2 - Di2, O4 = Di1 - Di3;
    const float s8  = (zb + Ai2) - (Ai1 + Ai3);
    const float s2  = E2 - O2, s14 = E2 + O2;
    const float s4  = E4 - O4, s12 = E4 + O4;
    const float s6  = E6 - O6, s10 = E6 + O6;

    const float mC  = Ci2 * c2;
    const float uE  = fmaf(Ci1, c1,  Ci3 * c3);
    const float u2E = fmaf(Ci1, c3, -(Ci3 * c1));
    const float ta  = z2p + mC, tb = z2p - mC;
    const float E1 = ta + uE, E7 = ta - uE, E3 = tb + u2E, E5 = tb - u2E;
    const float nS  = Si2 * c2;
    const float vO  = fmaf(Si1, c3,  Si3 * c1);
    const float v2O = fmaf(Si1, c1, -(Si3 * c3));
    const float wo = nS + sa4, w2o = nS - sa4;
    const float O1 = vO + wo, O7 = vO - wo, O3 = v2O + w2o, O5 = v2O - w2o;
    const float s1  = E1 - O1, s15 = E1 + O1;
    const float s3  = E3 - O3, s13 = E3 + O3;
    const float s5  = E5 - O5, s11 = E5 + O5;
    const float s7  = E7 - O7, s9  = E7 + O7;

    R0 = make_float4(0.f,               W8s(1,FOLD)*s1,   W8s(2,FOLD)*s2,   W8s(3,FOLD)*s3);
    R1 = make_float4(W8s(4,FOLD)*s4,    W8s(5,FOLD)*s5,   W8s(6,FOLD)*s6,   W8s(7,FOLD)*s7);
    R2 = make_float4(W8s(8,FOLD)*s8,    W8s(9,FOLD)*s9,   W8s(10,FOLD)*s10, W8s(11,FOLD)*s11);
    R3 = make_float4(W8s(12,FOLD)*s12,  W8s(13,FOLD)*s13, W8s(14,FOLD)*s14, W8s(15,FOLD)*s15);
}

// ---------------------------------------------------------------------------
// Fused kernel, 8 CTAs/SM, grid exactly 8 waves. Interior CTAs: constant
// geometry; B1/B2 remapped (thread t <-> frame/group t-3) so the B1 mag row
// and B2's q3 are register-resident. Edge CTAs: bounds-checked body.
// ---------------------------------------------------------------------------
__global__ void __launch_bounds__(NTHR, 8)
glim_kernel(const float* __restrict__ mag, float* __restrict__ out)
{
    __shared__ __align__(16) float sm[I_SMW];

    const int tid = threadIdx.x;
    const int bx  = blockIdx.x;
    const int b   = blockIdx.y;
    const float* magb = mag + (size_t)b * (KB9 * TFR);

    if (bx > 0 && bx < NT - 1) {
        // ================= INTERIOR body =================
        const int s0  = bx * OT;
        const int F0  = s0 >> 2;
        const int tM0 = F0 - 4;
        // constants: NFR=225, ngA=228, ngO=222, ROWS=232

        // ---- stage (single pass); keep own row in regs; m4 doubled ----
        float4 rS, rD; float rM4;
        if (tid < 232) {
            const float* gp = magb + (tM0 + tid);
            const float a0 = __ldg(gp);            const float a8 = __ldg(gp + 8 * TFR);
            const float a1 = __ldg(gp + 1 * TFR);  const float a7 = __ldg(gp + 7 * TFR);
            const float a2 = __ldg(gp + 2 * TFR);  const float a6 = __ldg(gp + 6 * TFR);
            const float a3 = __ldg(gp + 3 * TFR);  const float a5 = __ldg(gp + 5 * TFR);
            rS  = make_float4(a0 + a8, a1 + a7, a2 + a6, a3 + a5);
            rD  = make_float4(a0 - a8, a1 - a7, a2 - a6, a3 - a5);
            rM4 = 2.f * __ldg(gp + 4 * TFR);
            *reinterpret_cast<float4*>(sm + I_OFF_S + tid * 4) = rS;
            *reinterpret_cast<float4*>(sm + I_OFF_D + tid * 4) = rD;
            sm[I_OFF_M4 + tid] = rM4;
        }
        __syncthreads();

        // ---- Phase A: own row from regs, rows g+1..g+3 from smem ----
        float ay0 = 0.f, ay1 = 0.f, ay2 = 0.f, ay3 = 0.f;
        if (tid < 228) {
            const int g = tid;
            accA<3>(rS, rD, rM4, ay0, ay1, ay2, ay3);
            {   const float4 u0 = *reinterpret_cast<const float4*>(sm + I_OFF_S + (g + 1) * 4);
                const float4 u1 = *reinterpret_cast<const float4*>(sm + I_OFF_D + (g + 1) * 4);
                accA<2>(u0, u1, sm[I_OFF_M4 + g + 1], ay0, ay1, ay2, ay3); }
            {   const float4 u0 = *reinterpret_cast<const float4*>(sm + I_OFF_S + (g + 2) * 4);
                const float4 u1 = *reinterpret_cast<const float4*>(sm + I_OFF_D + (g + 2) * 4);
                accA<1>(u0, u1, sm[I_OFF_M4 + g + 2], ay0, ay1, ay2, ay3); }
            {   const float4 u0 = *reinterpret_cast<const float4*>(sm + I_OFF_S + (g + 3) * 4);
                const float4 u1 = *reinterpret_cast<const float4*>(sm + I_OFF_D + (g + 3) * 4);
                accA<0>(u0, u1, sm[I_OFF_M4 + g + 3], ay0, ay1, ay2, ay3); }
            *reinterpret_cast<float4*>(sm + I_OFF_WAV + g * 4) = make_float4(ay0, ay1, ay2, ay3);
        }
        __syncthreads();

        // ---- Phase B1 (remapped): thread t handles frame f = t-3 ----
        // A3 = own wav group (ay); MS/MD/m4 = own staged row t (= mag of
        // frame f+3). Only wav rows f..f+2 come from smem.
        float4 R3own;
        if (tid >= 3 && tid < 228) {
            const int f = tid - 3;
            const float4 A0 = *reinterpret_cast<const float4*>(sm + I_OFF_WAV + f * 4);
            const float4 A1 = *reinterpret_cast<const float4*>(sm + I_OFF_WAV + (f + 1) * 4);
            const float4 A2 = *reinterpret_cast<const float4*>(sm + I_OFF_WAV + (f + 2) * 4);
            const float4 A3 = make_float4(ay0, ay1, ay2, ay3);
            float4 R0, R1, R2, R3;
            processFrame<true>(A0, A1, A2, A3, rS, rD, rM4, R0, R1, R2, R3);
            *reinterpret_cast<float4*>(sm + I_OFF_P0 + f * 4) = R0;
            *reinterpret_cast<float4*>(sm + I_OFF_P1 + f * 4) = R1;
            *reinterpret_cast<float4*>(sm + I_OFF_P2 + f * 4) = R2;
            R3own = R3;                                      // P3 plane never stored
        }
        __syncthreads();

        // ---- Phase B2 (remapped): thread t outputs group g = t-3 ----
        if (tid >= 3 && tid < 225) {
            const int g = tid - 3;
            const float4 q2 = *reinterpret_cast<const float4*>(sm + I_OFF_P2 + (g + 1) * 4);
            const float4 q1 = *reinterpret_cast<const float4*>(sm + I_OFF_P1 + (g + 2) * 4);
            const float4 q0 = *reinterpret_cast<const float4*>(sm + I_OFF_P0 + (g + 3) * 4);
            float* outb = out + (size_t)b * LOUT + s0;
            *reinterpret_cast<float4*>(outb + 4 * g) = make_float4(
                (q0.x + q1.x) + (q2.x + R3own.x),
                (q0.y + q1.y) + (q2.y + R3own.y),
                (q0.z + q1.z) + (q2.z + R3own.z),
                (q0.w + q1.w) + (q2.w + R3own.w));
        }
    } else {
        // ================= EDGE body (tiles 0 and NT-1) =================
        const int s0   = bx * OT;
        const int nout = min(OT, LOUT - s0);
        const int F0   = s0 >> 2;
        const int TLO  = max(0, F0 - 1);
        const int THI  = min(TFR - 1, (s0 + nout + 7) >> 2);
        const int NFR  = THI - TLO + 1;
        const int tM0  = TLO - 3;
        const int ROWS = NFR + 7;                 // <= 231

        if (tid < ROWS) {
            const int tg = tM0 + tid;
            float4 S, D; float m4;
            if (tg >= 0 && tg < TFR) {
                const float* gp = magb + tg;
                const float a0 = __ldg(gp);            const float a8 = __ldg(gp + 8 * TFR);
                const float a1 = __ldg(gp + 1 * TFR);  const float a7 = __ldg(gp + 7 * TFR);
                const float a2 = __ldg(gp + 2 * TFR);  const float a6 = __ldg(gp + 6 * TFR);
                const float a3 = __ldg(gp + 3 * TFR);  const float a5 = __ldg(gp + 5 * TFR);
                m4 = 2.f * __ldg(gp + 4 * TFR);
                S = make_float4(a0 + a8, a1 + a7, a2 + a6, a3 + a5);
                D = make_float4(a0 - a8, a1 - a7, a2 - a6, a3 - a5);
            } else {
                S = make_float4(0.f, 0.f, 0.f, 0.f);
                D = S; m4 = 0.f;
            }
            *reinterpret_cast<float4*>(sm + I_OFF_S + tid * 4) = S;
            *reinterpret_cast<float4*>(sm + I_OFF_D + tid * 4) = D;
            sm[I_OFF_M4 + tid] = m4;              // doubled
        }
        __syncthreads();

        // Phase A (m4 plane intact here; holds 2*m4)
        const int ngA = NFR + 3;
        if (tid < ngA) {
            const int g     = tid;
            const int jbase = 4 * TLO - 8 + 4 * g;
            const int X     = TLO + g;
            if (jbase >= 0 && jbase + 3 < LOUT && X >= 3 && X <= TFR - 1) {
                float y0 = 0.f, y1 = 0.f, y2 = 0.f, y3 = 0.f;
                {   const float4 u0 = *reinterpret_cast<const float4*>(sm + I_OFF_S + g * 4);
                    const float4 u1 = *reinterpret_cast<const float4*>(sm + I_OFF_D + g * 4);
                    accA<3>(u0, u1, sm[I_OFF_M4 + g], y0, y1, y2, y3); }
                {   const float4 u0 = *reinterpret_cast<const float4*>(sm + I_OFF_S + (g + 1) * 4);
                    const float4 u1 = *reinterpret_cast<const float4*>(sm + I_OFF_D + (g + 1) * 4);
                    accA<2>(u0, u1, sm[I_OFF_M4 + g + 1], y0, y1, y2, y3); }
                {   const float4 u0 = *reinterpret_cast<const float4*>(sm + I_OFF_S + (g + 2) * 4);
                    const float4 u1 = *reinterpret_cast<const float4*>(sm + I_OFF_D + (g + 2) * 4);
                    accA<1>(u0, u1, sm[I_OFF_M4 + g + 2], y0, y1, y2, y3); }
                {   const float4 u0 = *reinterpret_cast<const float4*>(sm + I_OFF_S + (g + 3) * 4);
                    const float4 u1 = *reinterpret_cast<const float4*>(sm + I_OFF_D + (g + 3) * 4);
                    accA<0>(u0, u1, sm[I_OFF_M4 + g + 3], y0, y1, y2, y3); }
                *reinterpret_cast<float4*>(sm + I_OFF_WAV + g * 4) = make_float4(y0, y1, y2, y3);
            } else {
                float* wp = sm + I_OFF_WAV + g * 4;
                for (int r = 0; r < 4; r++) {
                    const int jg = jbase + r;
                    const int jr = (jg < 0) ? -jg : ((jg >= LOUT) ? 2 * LOUT - 2 - jg : jg);
                    const int p  = jr + 8;
                    const int Xp = p >> 2;
                    const int rr = p & 3;
                    float acc = 0.f, env = 0.f;
                    for (int jj = 0; jj < 4; jj++) {
                        const int tt = Xp - jj;
                        if (tt < 0 || tt >= TFR) continue;
                        const int n = rr + 4 * jj;
                        const float w = W16T[n];
                        const int row = tt - tM0;
                        const float* sp = sm + I_OFF_S + row * 4;
                        const float* dp = sm + I_OFF_D + row * 4;
                        float ssum;
                        if (n & 1) {
                            ssum = dp[0]
                                 + 2.f * (dp[1] * C8T[n & 15] + dp[2] * C8T[(2 * n) & 15] + dp[3] * C8T[(3 * n) & 15]);
                        } else {
                            // m4 plane holds 2*m4, which IS the needed
                            // coefficient (2 * m4 * cos): no extra factor.
                            ssum = sp[0]
                                 + 2.f * (sp[1] * C8T[n & 15] + sp[2] * C8T[(2 * n) & 15] + sp[3] * C8T[(3 * n) & 15])
                                 + sm[I_OFF_M4 + row] * C8T[(4 * n) & 15];
                        }
                        acc = fmaf(ssum, 0.0625f * w, acc);
                        env = fmaf(w, w, env);
                    }
                    wp[r] = acc / env;
                }
            }
        }
        __syncthreads();

        // Phase B1: m4 from GLOBAL (doubled); its smem slot becomes P3.
        if (tid < NFR) {
            const int f = tid;
            const float4 A0 = *reinterpret_cast<const float4*>(sm + I_OFF_WAV + f * 4);
            const float4 A1 = *reinterpret_cast<const float4*>(sm + I_OFF_WAV + (f + 1) * 4);
            const float4 A2 = *reinterpret_cast<const float4*>(sm + I_OFF_WAV + (f + 2) * 4);
            const float4 A3 = *reinterpret_cast<const float4*>(sm + I_OFF_WAV + (f + 3) * 4);
            const float4 MS = *reinterpret_cast<const float4*>(sm + I_OFF_S + (f + 3) * 4);
            const float4 MD = *reinterpret_cast<const float4*>(sm + I_OFF_D + (f + 3) * 4);
            const float m4v = 2.f * __ldg(magb + 4 * TFR + (tM0 + f + 3));
            float4 R0, R1, R2, R3;
            processFrame<false>(A0, A1, A2, A3, MS, MD, m4v, R0, R1, R2, R3);
            *reinterpret_cast<float4*>(sm + I_OFF_P0 + f * 4) = R0;
            *reinterpret_cast<float4*>(sm + I_OFF_P1 + f * 4) = R1;
            *reinterpret_cast<float4*>(sm + I_OFF_P2 + f * 4) = R2;
            *reinterpret_cast<float4*>(sm + I_OFF_P3 + f * 4) = R3;
        }
        __syncthreads();

        // Phase B2
        const int ngO = (nout + 3) >> 2;
        float* outb = out + (size_t)b * LOUT + s0;
        if (tid < ngO) {
            const int g = tid;
            const int X = F0 + g + 2;
            const bool wholeGroup = (4 * g + 3 < nout);
            if (wholeGroup && X - 3 >= TLO && X <= THI) {
                const int Rb = X - TLO - 3;
                const float4 q3 = *reinterpret_cast<const float4*>(sm + I_OFF_P3 + Rb * 4);
                const float4 q2 = *reinterpret_cast<const float4*>(sm + I_OFF_P2 + (Rb + 1) * 4);
                const float4 q1 = *reinterpret_cast<const float4*>(sm + I_OFF_P1 + (Rb + 2) * 4);
                const float4 q0 = *reinterpret_cast<const float4*>(sm + I_OFF_P0 + (Rb + 3) * 4);
                *reinterpret_cast<float4*>(outb + 4 * g) = make_float4(
                    ((q0.x + q1.x) + (q2.x + q3.x)) * EINVc(0),
                    ((q0.y + q1.y) + (q2.y + q3.y)) * EINVc(1),
                    ((q0.z + q1.z) + (q2.z + q3.z)) * EINVc(2),
                    ((q0.w + q1.w) + (q2.w + q3.w)) * EINVc(3));
            } else {
                for (int r = 0; r < 4; r++) {
                    const int so = 4 * g + r;
                    if (so >= nout) break;
                    const int s  = s0 + so;
                    const int p  = s + 8;
                    const int Xp = p >> 2;
                    const int rr = p & 3;
                    float acc = 0.f, env = 0.f;
                    for (int jj = 0; jj < 4; jj++) {
                        const int tt = Xp - jj;
                        if (tt < TLO || tt > THI) continue;
                        const int n = rr + 4 * jj;
                        const float w = W16T[n];
                        acc += sm[I_OFF_P0 + (n >> 2) * PPLANE + (tt - TLO) * 4 + (n & 3)];
                        env = fmaf(w, w, env);
                    }
                    outb[so] = acc / env;
                }
            }
        }
    }
}

// ---------------------------------------------------------------------------
extern "C" void kernel_launch(void* const* d_in, const int* in_sizes, int n_in,
                              void* d_out, int out_size)
{
    (void)in_sizes; (void)n_in; (void)out_size;
    const float* mag = (const float*)d_in[0];
    float* out = (float*)d_out;
    // Maximize shared carveout; 25.5 KB/CTA -> 8 CTAs/SM; grid = 8 full waves.
    cudaFuncSetAttribute(glim_kernel, cudaFuncAttributePreferredSharedMemoryCarveout, 100);
    dim3 grid(NT, BATCH);
    glim_kernel<<<grid, NTHR>>>(mag, out);
}

// round 17
// speedup vs baseline: 1.0951x; 1.0571x over previous
#include <cuda_runtime.h>

// ---------------------------------------------------------------------------
// Problem constants
// ---------------------------------------------------------------------------
constexpr int TFR   = 65536;
constexpr int KB9   = 9;
constexpr int BATCH = 32;
constexpr int LOUT  = (TFR - 1) * 4;            // 262140

constexpr int OT   = 980;                       // output samples per tile
constexpr int NT   = (LOUT + OT - 1) / OT;      // 268 tiles
constexpr int NTHR = 256;

// Interior geometry (compile-time): NFR=248, ngA=251, ngO=245, ROWS=255.
constexpr int I_OFF_S   = 0;                     // S plane: 255 x 4
constexpr int I_OFF_D   = 1020;                  // D plane: 255 x 4
constexpr int I_OFF_WAV = 2040;                  // wav plane: 251 x 4
constexpr int I_OFF_P0  = 3044;                  // P chunk planes: 248 x 4 each
constexpr int I_OFF_P1  = 4036;
constexpr int I_OFF_P2  = 5028;
constexpr int I_OFF_P3  = 6020;                  // P3 plane (EDGE only) / m4 overlay
constexpr int I_OFF_M4  = 6020;                  // m4[t] (DOUBLED) at P3 base + t
constexpr int I_SMW     = 7012;                  // 28048 bytes -> 8 CTAs/SM
constexpr int PPLANE    = 992;                   // words per P plane

// ---------------------------------------------------------------------------
// Compile-time twiddles (all angles multiples of pi/8)
// ---------------------------------------------------------------------------
#define HD __host__ __device__ __forceinline__

HD constexpr float cos8c(int m) {
    m &= 15;
    const int mm = m & 7;
    const float v =
        (mm == 0) ?  1.0f :
        (mm == 1) ?  0.92387953251128674f :
        (mm == 2) ?  0.70710678118654752f :
        (mm == 3) ?  0.38268343236508977f :
        (mm == 4) ?  0.0f :
        (mm == 5) ? -0.38268343236508977f :
        (mm == 6) ? -0.70710678118654752f :
                    -0.92387953251128674f;
    return (m & 8) ? -v : v;
}
HD constexpr float sin8c(int m) { return cos8c(m + 12); }
HD constexpr float wwinc(int n) { return 0.5f - 0.5f * cos8c(n); }   // hann(16)
HD constexpr float CSc(int k, int n) { return ((k == 0) ? 1.0f : 2.0f) * 0.0625f * cos8c(k * n) * wwinc(n); }
HD constexpr float envsum(int r) {
    return wwinc(r)      * wwinc(r)      + wwinc(r + 4)  * wwinc(r + 4)
         + wwinc(r + 8)  * wwinc(r + 8)  + wwinc(r + 12) * wwinc(r + 12);
}
HD constexpr float EINVc(int r) { return 1.0f / envsum(r); }
HD constexpr float CSF(int k, int n) { return CSc(k, n) * EINVc(n & 3); }
// m4 is stored DOUBLED; its accA coefficient carries the compensating 0.5.
HD constexpr float CSF4h(int n) { return CSF(4, n) * 0.5f; }
// P-row scale: window/16 (the extra 0.5 compensates the un-halved mv),
// optionally with 1/env folded (interior fast path).
HD constexpr float W8s(int n, bool fold) {
    return wwinc(n) * 0.0625f * (fold ? EINVc(n & 3) : 1.0f);
}

// Runtime tables (edge fallbacks only)
__constant__ float C8T[16] = { cos8c(0), cos8c(1), cos8c(2), cos8c(3), cos8c(4), cos8c(5), cos8c(6), cos8c(7),
                               cos8c(8), cos8c(9), cos8c(10), cos8c(11), cos8c(12), cos8c(13), cos8c(14), cos8c(15) };
__constant__ float W16T[16] = { wwinc(0), wwinc(1), wwinc(2), wwinc(3), wwinc(4), wwinc(5), wwinc(6), wwinc(7),
                                wwinc(8), wwinc(9), wwinc(10), wwinc(11), wwinc(12), wwinc(13), wwinc(14), wwinc(15) };

// ---------------------------------------------------------------------------
// Phase-A accumulator (env folded; m4 operand arrives doubled).
// ---------------------------------------------------------------------------
template<int JJ>
__device__ __forceinline__ void accA(const float4 u0, const float4 u1, const float m4,
                                     float& y0, float& y1, float& y2, float& y3)
{
    { constexpr int n = 4 * JJ + 0;
      if (CSF(0,n)  != 0.f) y0 = fmaf(u0.x, CSF(0,n),  y0);
      if (CSF(1,n)  != 0.f) y0 = fmaf(u0.y, CSF(1,n),  y0);
      if (CSF(2,n)  != 0.f) y0 = fmaf(u0.z, CSF(2,n),  y0);
      if (CSF(3,n)  != 0.f) y0 = fmaf(u0.w, CSF(3,n),  y0);
      if (CSF4h(n)  != 0.f) y0 = fmaf(m4,   CSF4h(n),  y0); }
    { constexpr int n = 4 * JJ + 1;
      if (CSF(0,n)  != 0.f) y1 = fmaf(u1.x, CSF(0,n),  y1);
      if (CSF(1,n)  != 0.f) y1 = fmaf(u1.y, CSF(1,n),  y1);
      if (CSF(2,n)  != 0.f) y1 = fmaf(u1.z, CSF(2,n),  y1);
      if (CSF(3,n)  != 0.f) y1 = fmaf(u1.w, CSF(3,n),  y1); }
    { constexpr int n = 4 * JJ + 2;
      if (CSF(0,n)  != 0.f) y2 = fmaf(u0.x, CSF(0,n),  y2);
      if (CSF(1,n)  != 0.f) y2 = fmaf(u0.y, CSF(1,n),  y2);
      if (CSF(2,n)  != 0.f) y2 = fmaf(u0.z, CSF(2,n),  y2);
      if (CSF(3,n)  != 0.f) y2 = fmaf(u0.w, CSF(3,n),  y2);
      if (CSF4h(n)  != 0.f) y2 = fmaf(m4,   CSF4h(n),  y2); }
    { constexpr int n = 4 * JJ + 3;
      if (CSF(0,n)  != 0.f) y3 = fmaf(u1.x, CSF(0,n),  y3);
      if (CSF(1,n)  != 0.f) y3 = fmaf(u1.y, CSF(1,n),  y3);
      if (CSF(2,n)  != 0.f) y3 = fmaf(u1.z, CSF(2,n),  y3);
      if (CSF(3,n)  != 0.f) y3 = fmaf(u1.w, CSF(3,n),  y3); }
}

// ---------------------------------------------------------------------------
// B1 frame processing, FFT-folded; result in registers.
// mv is UNSCALED (S+-D, m4 doubled); the compensating 0.5 lives in W8s.
// FOLD=true folds 1/env into the P-row scales (interior fast path only).
// ---------------------------------------------------------------------------
template<bool FOLD>
__device__ __forceinline__ void processFrame(const float4 A0, const float4 A1,
                                             const float4 A2, const float4 A3,
                                             const float4 MS, const float4 MD, const float m4v,
                                             float4& R0, float4& R1, float4& R2, float4& R3)
{
    constexpr float c1 = 0.92387953251128674f;   // cos(pi/8)
    constexpr float c2 = 0.70710678118654752f;   // cos(pi/4)
    constexpr float c3 = 0.38268343236508977f;   // cos(3pi/8)

    const float x8 = A2.x;
    const float e1 = wwinc(1) * (A0.y + A3.w), o1 = wwinc(1) * (A0.y - A3.w);
    const float e2 = wwinc(2) * (A0.z + A3.z), o2 = wwinc(2) * (A0.z - A3.z);
    const float e3 = wwinc(3) * (A0.w + A3.y), o3 = wwinc(3) * (A0.w - A3.y);
    const float e4 = wwinc(4) * (A1.x + A3.x), o4 = wwinc(4) * (A1.x - A3.x);
    const float e5 = wwinc(5) * (A1.y + A2.w), o5 = wwinc(5) * (A1.y - A2.w);
    const float e6 = wwinc(6) * (A1.z + A2.z), o6 = wwinc(6) * (A1.z - A2.z);
    const float e7 = wwinc(7) * (A1.w + A2.y), o7 = wwinc(7) * (A1.w - A2.y);

    const float es1 = e1 + e7, es2 = e2 + e6, es3 = e3 + e5;
    const float ed1 = e1 - e7, ed2 = e2 - e6, ed3 = e3 - e5;
    const float os1 = o1 + o7, os2 = o2 + o6, os3 = o3 + o5;
    const float od1 = o1 - o7, od2 = o2 - o6, od3 = o3 - o5;

    float re[9], im[9];
    {   const float t1 = c2 * (es1 - es3);
        const float t2 = x8 - e4, t3 = x8 + e4;
        const float q  = es1 + es3;
        const float Aa = t3 + es2;
        re[0] = Aa + q;  re[8] = Aa - q;
        re[2] = t2 + t1; re[6] = t2 - t1;
        re[4] = t3 - es2; }
    {   const float m  = ed2 * c2;
        const float v  = m - x8, w = -m - x8;
        const float u  = fmaf(ed1, c1,  ed3 * c3);
        const float u2 = fmaf(ed1, c3, -(ed3 * c1));
        re[1] = v + u;  re[7] = v - u;
        re[3] = w + u2; re[5] = w - u2; }
    {   const float a  = fmaf(os1, c3,  os3 * c1);
        const float b  = fmaf(os2, c2,  o4);
        const float a2 = fmaf(os1, c1, -(os3 * c3));
        const float b2 = fmaf(os2, c2, -o4);
        im[1] = -(a + b);   im[3] = -(a2 + b2);
        im[5] = b2 - a2;    im[7] = b - a; }
    {   const float t4 = c2 * (od1 + od3);
        im[2] = -(t4 + od2); im[6] = od2 - t4; im[4] = od3 - od1; }

    // UNSCALED magnitudes (2x true values); 0.5 compensated in W8s.
    float mv[9];
    mv[0] = MS.x + MD.x;  mv[8] = MS.x - MD.x;
    mv[1] = MS.y + MD.y;  mv[7] = MS.y - MD.y;
    mv[2] = MS.z + MD.z;  mv[6] = MS.z - MD.z;
    mv[3] = MS.w + MD.w;  mv[5] = MS.w - MD.w;
    mv[4] = m4v;          // arrives doubled

    // Branchless phase normalization: eps folded into the accumulation
    // (1e-30 is a normal float; perturbs n2 ~ O(1e-28) relative).
    float ca[9], sa[9];
    ca[0] = copysignf(mv[0], re[0]);
    ca[8] = copysignf(mv[8], re[8]);
    #pragma unroll
    for (int k = 1; k < 8; k++) {
        const float n2 = fmaf(re[k], re[k], fmaf(im[k], im[k], 1e-30f));
        const float u  = mv[k] * rsqrtf(n2);
        ca[k] = re[k] * u;
        sa[k] = im[k] * u;
    }

    const float Ai1 = ca[1] + ca[7], Ai2 = ca[2] + ca[6], Ai3 = ca[3] + ca[5];
    const float Ci1 = ca[1] - ca[7], Ci2 = ca[2] - ca[6], Ci3 = ca[3] - ca[5];
    const float Si1 = sa[1] + sa[7], Si2 = sa[2] + sa[6], Si3 = sa[3] + sa[5];
    const float Di1 = sa[1] - sa[7], Di2 = sa[2] - sa[6], Di3 = sa[3] - sa[5];
    const float z2  = 0.5f * (ca[0] + ca[8]);
    const float z2p = 0.5f * (ca[0] - ca[8]);
    const float ca4 = ca[4], sa4 = sa[4];

    const float h1 = c2 * (Ai1 - Ai3);
    const float h2 = c2 * (Di1 + Di3);
    const float za = z2 - ca4, zb = z2 + ca4;
    const float E2 = za + h1, E6 = za - h1, E4 = zb - Ai2;
    const float O2 = h2 + Di2, O6 = h2 - Di2, O4 = Di1 - Di3;
    const float s8  = (zb + Ai2) - (Ai1 + Ai3);
    const float s2  = E2 - O2, s14 = E2 + O2;
    const float s4  = E4 - O4, s12 = E4 + O4;
    const float s6  = E6 - O6, s10 = E6 + O6;

    const float mC  = Ci2 * c2;
    const float uE  = fmaf(Ci1, c1,  Ci3 * c3);
    const float u2E = fmaf(Ci1, c3, -(Ci3 * c1));
    const float ta  = z2p + mC, tb = z2p - mC;
    const float E1 = ta + uE, E7 = ta - uE, E3 = tb + u2E, E5 = tb - u2E;
    const float nS  = Si2 * c2;
    const float vO  = fmaf(Si1, c3,  Si3 * c1);
    const float v2O = fmaf(Si1, c1, -(Si3 * c3));
    const float wo = nS + sa4, w2o = nS - sa4;
    const float O1 = vO + wo, O7 = vO - wo, O3 = v2O + w2o, O5 = v2O - w2o;
    const float s1  = E1 - O1, s15 = E1 + O1;
    const float s3  = E3 - O3, s13 = E3 + O3;
    const float s5  = E5 - O5, s11 = E5 + O5;
    const float s7  = E7 - O7, s9  = E7 + O7;

    R0 = make_float4(0.f,               W8s(1,FOLD)*s1,   W8s(2,FOLD)*s2,   W8s(3,FOLD)*s3);
    R1 = make_float4(W8s(4,FOLD)*s4,    W8s(5,FOLD)*s5,   W8s(6,FOLD)*s6,   W8s(7,FOLD)*s7);
    R2 = make_float4(W8s(8,FOLD)*s8,    W8s(9,FOLD)*s9,   W8s(10,FOLD)*s10, W8s(11,FOLD)*s11);
    R3 = make_float4(W8s(12,FOLD)*s12,  W8s(13,FOLD)*s13, W8s(14,FOLD)*s14, W8s(15,FOLD)*s15);
}

// ---------------------------------------------------------------------------
// Fused kernel, 8 CTAs/SM. Interior CTAs: constant geometry; B1/B2 remapped
// (thread t <-> frame/group t-3) so the B1 mag row and B2's q3 are
// register-resident. Edge CTAs: bounds-checked body on the same planes.
// ---------------------------------------------------------------------------
__global__ void __launch_bounds__(NTHR, 8)
glim_kernel(const float* __restrict__ mag, float* __restrict__ out)
{
    __shared__ __align__(16) float sm[I_SMW];

    const int tid = threadIdx.x;
    const int bx  = blockIdx.x;
    const int b   = blockIdx.y;
    const float* magb = mag + (size_t)b * (KB9 * TFR);

    if (bx > 0 && bx < NT - 1) {
        // ================= INTERIOR body =================
        const int s0  = bx * OT;
        const int F0  = s0 >> 2;
        const int tM0 = F0 - 4;
        // constants: NFR=248, ngA=251, ngO=245, ROWS=255

        // ---- stage (single pass); keep own row in regs; m4 doubled ----
        float4 rS, rD; float rM4;
        if (tid < 255) {
            const float* gp = magb + (tM0 + tid);
            const float a0 = __ldg(gp);            const float a8 = __ldg(gp + 8 * TFR);
            const float a1 = __ldg(gp + 1 * TFR);  const float a7 = __ldg(gp + 7 * TFR);
            const float a2 = __ldg(gp + 2 * TFR);  const float a6 = __ldg(gp + 6 * TFR);
            const float a3 = __ldg(gp + 3 * TFR);  const float a5 = __ldg(gp + 5 * TFR);
            rS  = make_float4(a0 + a8, a1 + a7, a2 + a6, a3 + a5);
            rD  = make_float4(a0 - a8, a1 - a7, a2 - a6, a3 - a5);
            rM4 = 2.f * __ldg(gp + 4 * TFR);
            *reinterpret_cast<float4*>(sm + I_OFF_S + tid * 4) = rS;
            *reinterpret_cast<float4*>(sm + I_OFF_D + tid * 4) = rD;
            sm[I_OFF_M4 + tid] = rM4;
        }
        __syncthreads();

        // ---- Phase A: own row from regs, rows g+1..g+3 from smem ----
        float ay0 = 0.f, ay1 = 0.f, ay2 = 0.f, ay3 = 0.f;
        if (tid < 251) {
            const int g = tid;
            accA<3>(rS, rD, rM4, ay0, ay1, ay2, ay3);
            {   const float4 u0 = *reinterpret_cast<const float4*>(sm + I_OFF_S + (g + 1) * 4);
                const float4 u1 = *reinterpret_cast<const float4*>(sm + I_OFF_D + (g + 1) * 4);
                accA<2>(u0, u1, sm[I_OFF_M4 + g + 1], ay0, ay1, ay2, ay3); }
            {   const float4 u0 = *reinterpret_cast<const float4*>(sm + I_OFF_S + (g + 2) * 4);
                const float4 u1 = *reinterpret_cast<const float4*>(sm + I_OFF_D + (g + 2) * 4);
                accA<1>(u0, u1, sm[I_OFF_M4 + g + 2], ay0, ay1, ay2, ay3); }
            {   const float4 u0 = *reinterpret_cast<const float4*>(sm + I_OFF_S + (g + 3) * 4);
                const float4 u1 = *reinterpret_cast<const float4*>(sm + I_OFF_D + (g + 3) * 4);
                accA<0>(u0, u1, sm[I_OFF_M4 + g + 3], ay0, ay1, ay2, ay3); }
            *reinterpret_cast<float4*>(sm + I_OFF_WAV + g * 4) = make_float4(ay0, ay1, ay2, ay3);
        }
        __syncthreads();

        // ---- Phase B1 (remapped): thread t handles frame f = t-3 ----
        // A3 = own wav group (ay); MS/MD/m4 = own staged row t (= mag of
        // frame f+3). Only wav rows f..f+2 come from smem.
        float4 R3own;
        if (tid >= 3 && tid < 251) {
            const int f = tid - 3;
            const float4 A0 = *reinterpret_cast<const float4*>(sm + I_OFF_WAV + f * 4);
            const float4 A1 = *reinterpret_cast<const float4*>(sm + I_OFF_WAV + (f + 1) * 4);
            const float4 A2 = *reinterpret_cast<const float4*>(sm + I_OFF_WAV + (f + 2) * 4);
            const float4 A3 = make_float4(ay0, ay1, ay2, ay3);
            float4 R0, R1, R2, R3;
            processFrame<true>(A0, A1, A2, A3, rS, rD, rM4, R0, R1, R2, R3);
            *reinterpret_cast<float4*>(sm + I_OFF_P0 + f * 4) = R0;
            *reinterpret_cast<float4*>(sm + I_OFF_P1 + f * 4) = R1;
            *reinterpret_cast<float4*>(sm + I_OFF_P2 + f * 4) = R2;
            R3own = R3;                                      // P3 plane never stored
        }
        __syncthreads();

        // ---- Phase B2 (remapped): thread t outputs group g = t-3 ----
        if (tid >= 3 && tid < 248) {
            const int g = tid - 3;
            const float4 q2 = *reinterpret_cast<const float4*>(sm + I_OFF_P2 + (g + 1) * 4);
            const float4 q1 = *reinterpret_cast<const float4*>(sm + I_OFF_P1 + (g + 2) * 4);
            const float4 q0 = *reinterpret_cast<const float4*>(sm + I_OFF_P0 + (g + 3) * 4);
            float* outb = out + (size_t)b * LOUT + s0;
            *reinterpret_cast<float4*>(outb + 4 * g) = make_float4(
                (q0.x + q1.x) + (q2.x + R3own.x),
                (q0.y + q1.y) + (q2.y + R3own.y),
                (q0.z + q1.z) + (q2.z + R3own.z),
                (q0.w + q1.w) + (q2.w + R3own.w));
        }
    } else {
        // ================= EDGE body (tiles 0 and NT-1) =================
        const int s0   = bx * OT;
        const int nout = min(OT, LOUT - s0);
        const int F0   = s0 >> 2;
        const int TLO  = max(0, F0 - 1);
        const int THI  = min(TFR - 1, (s0 + nout + 7) >> 2);
        const int NFR  = THI - TLO + 1;
        const int tM0  = TLO - 3;
        const int ROWS = NFR + 7;                 // <= 254

        if (tid < ROWS) {
            const int tg = tM0 + tid;
            float4 S, D; float m4;
            if (tg >= 0 && tg < TFR) {
                const float* gp = magb + tg;
                const float a0 = __ldg(gp);            const float a8 = __ldg(gp + 8 * TFR);
                const float a1 = __ldg(gp + 1 * TFR);  const float a7 = __ldg(gp + 7 * TFR);
                const float a2 = __ldg(gp + 2 * TFR);  const float a6 = __ldg(gp + 6 * TFR);
                const float a3 = __ldg(gp + 3 * TFR);  const float a5 = __ldg(gp + 5 * TFR);
                m4 = 2.f * __ldg(gp + 4 * TFR);
                S = make_float4(a0 + a8, a1 + a7, a2 + a6, a3 + a5);
                D = make_float4(a0 - a8, a1 - a7, a2 - a6, a3 - a5);
            } else {
                S = make_float4(0.f, 0.f, 0.f, 0.f);
                D = S; m4 = 0.f;
            }
            *reinterpret_cast<float4*>(sm + I_OFF_S + tid * 4) = S;
            *reinterpret_cast<float4*>(sm + I_OFF_D + tid * 4) = D;
            sm[I_OFF_M4 + tid] = m4;              // doubled
        }
        __syncthreads();

        // Phase A (m4 plane intact here; holds 2*m4)
        const int ngA = NFR + 3;
        if (tid < ngA) {
            const int g     = tid;
            const int jbase = 4 * TLO - 8 + 4 * g;
            const int X     = TLO + g;
            if (jbase >= 0 && jbase + 3 < LOUT && X >= 3 && X <= TFR - 1) {
                float y0 = 0.f, y1 = 0.f, y2 = 0.f, y3 = 0.f;
                {   const float4 u0 = *reinterpret_cast<const float4*>(sm + I_OFF_S + g * 4);
                    const float4 u1 = *reinterpret_cast<const float4*>(sm + I_OFF_D + g * 4);
                    accA<3>(u0, u1, sm[I_OFF_M4 + g], y0, y1, y2, y3); }
                {   const float4 u0 = *reinterpret_cast<const float4*>(sm + I_OFF_S + (g + 1) * 4);
                    const float4 u1 = *reinterpret_cast<const float4*>(sm + I_OFF_D + (g + 1) * 4);
                    accA<2>(u0, u1, sm[I_OFF_M4 + g + 1], y0, y1, y2, y3); }
                {   const float4 u0 = *reinterpret_cast<const float4*>(sm + I_OFF_S + (g + 2) * 4);
                    const float4 u1 = *reinterpret_cast<const float4*>(sm + I_OFF_D + (g + 2) * 4);
                    accA<1>(u0, u1, sm[I_OFF_M4 + g + 2], y0, y1, y2, y3); }
                {   const float4 u0 = *reinterpret_cast<const float4*>(sm + I_OFF_S + (g + 3) * 4);
                    const float4 u1 = *reinterpret_cast<const float4*>(sm + I_OFF_D + (g + 3) * 4);
                    accA<0>(u0, u1, sm[I_OFF_M4 + g + 3], y0, y1, y2, y3); }
                *reinterpret_cast<float4*>(sm + I_OFF_WAV + g * 4) = make_float4(y0, y1, y2, y3);
            } else {
                float* wp = sm + I_OFF_WAV + g * 4;
                for (int r = 0; r < 4; r++) {
                    const int jg = jbase + r;
                    const int jr = (jg < 0) ? -jg : ((jg >= LOUT) ? 2 * LOUT - 2 - jg : jg);
                    const int p  = jr + 8;
                    const int Xp = p >> 2;
                    const int rr = p & 3;
                    float acc = 0.f, env = 0.f;
                    for (int jj = 0; jj < 4; jj++) {
                        const int tt = Xp - jj;
                        if (tt < 0 || tt >= TFR) continue;
                        const int n = rr + 4 * jj;
                        const float w = W16T[n];
                        const int row = tt - tM0;
                        const float* sp = sm + I_OFF_S + row * 4;
                        const float* dp = sm + I_OFF_D + row * 4;
                        float ssum;
                        if (n & 1) {
                            ssum = dp[0]
                                 + 2.f * (dp[1] * C8T[n & 15] + dp[2] * C8T[(2 * n) & 15] + dp[3] * C8T[(3 * n) & 15]);
                        } else {
                            // m4 plane holds 2*m4, which IS the needed
                            // coefficient (2 * m4 * cos): no extra factor.
                            ssum = sp[0]
                                 + 2.f * (sp[1] * C8T[n & 15] + sp[2] * C8T[(2 * n) & 15] + sp[3] * C8T[(3 * n) & 15])
                                 + sm[I_OFF_M4 + row] * C8T[(4 * n) & 15];
                        }
                        acc = fmaf(ssum, 0.0625f * w, acc);
                        env = fmaf(w, w, env);
                    }
                    wp[r] = acc / env;
                }
            }
        }
        __syncthreads();

        // Phase B1: m4 from GLOBAL (doubled); its smem slot becomes P3.
        if (tid < NFR) {
            const int f = tid;
            const float4 A0 = *reinterpret_cast<const float4*>(sm + I_OFF_WAV + f * 4);
            const float4 A1 = *reinterpret_cast<const float4*>(sm + I_OFF_WAV + (f + 1) * 4);
            const float4 A2 = *reinterpret_cast<const float4*>(sm + I_OFF_WAV + (f + 2) * 4);
            const float4 A3 = *reinterpret_cast<const float4*>(sm + I_OFF_WAV + (f + 3) * 4);
            const float4 MS = *reinterpret_cast<const float4*>(sm + I_OFF_S + (f + 3) * 4);
            const float4 MD = *reinterpret_cast<const float4*>(sm + I_OFF_D + (f + 3) * 4);
            const float m4v = 2.f * __ldg(magb + 4 * TFR + (tM0 + f + 3));
            float4 R0, R1, R2, R3;
            processFrame<false>(A0, A1, A2, A3, MS, MD, m4v, R0, R1, R2, R3);
            *reinterpret_cast<float4*>(sm + I_OFF_P0 + f * 4) = R0;
            *reinterpret_cast<float4*>(sm + I_OFF_P1 + f * 4) = R1;
            *reinterpret_cast<float4*>(sm + I_OFF_P2 + f * 4) = R2;
            *reinterpret_cast<float4*>(sm + I_OFF_P3 + f * 4) = R3;
        }
        __syncthreads();

        // Phase B2
        const int ngO = (nout + 3) >> 2;
        float* outb = out + (size_t)b * LOUT + s0;
        if (tid < ngO) {
            const int g = tid;
            const int X = F0 + g + 2;
            const bool wholeGroup = (4 * g + 3 < nout);
            if (wholeGroup && X - 3 >= TLO && X <= THI) {
                const int Rb = X - TLO - 3;
                const float4 q3 = *reinterpret_cast<const float4*>(sm + I_OFF_P3 + Rb * 4);
                const float4 q2 = *reinterpret_cast<const float4*>(sm + I_OFF_P2 + (Rb + 1) * 4);
                const float4 q1 = *reinterpret_cast<const float4*>(sm + I_OFF_P1 + (Rb + 2) * 4);
                const float4 q0 = *reinterpret_cast<const float4*>(sm + I_OFF_P0 + (Rb + 3) * 4);
                *reinterpret_cast<float4*>(outb + 4 * g) = make_float4(
                    ((q0.x + q1.x) + (q2.x + q3.x)) * EINVc(0),
                    ((q0.y + q1.y) + (q2.y + q3.y)) * EINVc(1),
                    ((q0.z + q1.z) + (q2.z + q3.z)) * EINVc(2),
                    ((q0.w + q1.w) + (q2.w + q3.w)) * EINVc(3));
            } else {
                for (int r = 0; r < 4; r++) {
                    const int so = 4 * g + r;
                    if (so >= nout) break;
                    const int s  = s0 + so;
                    const int p  = s + 8;
                    const int Xp = p >> 2;
                    const int rr = p & 3;
                    float acc = 0.f, env = 0.f;
                    for (int jj = 0; jj < 4; jj++) {
                        const int tt = Xp - jj;
                        if (tt < TLO || tt > THI) continue;
                        const int n = rr + 4 * jj;
                        const float w = W16T[n];
                        acc += sm[I_OFF_P0 + (n >> 2) * PPLANE + (tt - TLO) * 4 + (n & 3)];
                        env = fmaf(w, w, env);
                    }
                    outb[so] = acc / env;
                }
            }
        }
    }
}

// ---------------------------------------------------------------------------
extern "C" void kernel_launch(void* const* d_in, const int* in_sizes, int n_in,
                              void* d_out, int out_size)
{
    (void)in_sizes; (void)n_in; (void)out_size;
    const float* mag = (const float*)d_in[0];
    float* out = (float*)d_out;
    // Maximize shared carveout; 28.0 KB/CTA -> 8 CTAs/SM.
    cudaFuncSetAttribute(glim_kernel, cudaFuncAttributePreferredSharedMemoryCarveout, 100);
    dim3 grid(NT, BATCH);
    glim_kernel<<<grid, NTHR>>>(mag, out);
}